// round 11
// baseline (speedup 1.0000x reference)
#include <cuda_runtime.h>

#define NB 16
#define NS 256
#define NT 400
#define NMEL 80
#define NPRE 256
#define NENC 512
#define NH 1024
#define NATT 128
#define NFILT 32
#define KC 31
#define GRID 148
#define TPB 512
#define SMEM_BYTES 131072

struct Params {
    const float *memory, *dec_in, *Wpre1, *Wpre2, *Wih_a, *Whh_a, *bih_a, *bhh_a;
    const float *Wq, *Wm, *v, *Wc, *Wld, *Wih_d, *Whh_d, *bih_d, *bhh_d;
    const float *Wproj, *bproj, *Wgate, *bgate;
    const int* mlen;
    float *out_mel, *out_gate, *out_align;
};

__device__ float g_xs[NT * NB * NPRE];
__device__ float g_pm[NB * NS * NATT];
__device__ float g_ah[2][NB * NH];
__device__ float g_ac[NB * NH];
__device__ float g_dh[NB * NH];
__device__ float g_dc[NB * NH];
__device__ float g_aw[NB * NS];
__device__ float g_awc[NB * NS];
__device__ float g_ctx[NB * NENC];
__device__ unsigned g_cnt = 0;
__device__ unsigned g_gen = 0;

__device__ __forceinline__ void grid_sync() {
    __threadfence();
    __syncthreads();
    if (threadIdx.x == 0) {
        volatile unsigned* gp = &g_gen;
        unsigned gen = *gp;
        if (atomicAdd(&g_cnt, 1u) == GRID - 1) {
            g_cnt = 0;
            __threadfence();
            *gp = gen + 1;
        } else {
            while (*gp == gen) { }
        }
        __threadfence();
    }
    __syncthreads();
}

__device__ __forceinline__ float sigf(float x) { return 1.0f / (1.0f + __expf(-x)); }

__device__ __forceinline__ void wred16(float* a) {
#pragma unroll
    for (int off = 16; off > 0; off >>= 1)
#pragma unroll
        for (int i = 0; i < 16; ++i)
            a[i] += __shfl_xor_sync(0xffffffffu, a[i], off);
}

__device__ __forceinline__ float pick16(const float* a, int lane) {
    float v = a[0];
#pragma unroll
    for (int b = 1; b < 16; ++b)
        if (lane == b) v = a[b];
    return v;
}

// 2-gate-row x 16-batch GEMM accumulation over NCH chunks of 128 k's.
// Compile-time XSTRIDE -> LDS base+immediate addressing.
// Weight prefetch (next chunk) + x double-buffer (next batch) keep
// both the LDG and LDS latencies off the critical path.
template <int XSTRIDE, int NCH>
__device__ __forceinline__ void gemm2_accum(
    const float4* __restrict__ W0, const float4* __restrict__ W1,
    const float* __restrict__ sX, int lane,
    float* A0, float* A1)
{
    float4 c0 = W0[lane], c1 = W1[lane];
#pragma unroll
    for (int c = 0; c < NCH; ++c) {
        const int nidx = ((c + 1 < NCH) ? (c + 1) : c) * 32 + lane;
        float4 n0 = W0[nidx], n1 = W1[nidx];
        const float* xb = sX + c * 128 + lane * 4;
        float4 xc = *(const float4*)(xb);
#pragma unroll
        for (int b = 0; b < 16; ++b) {
            float4 xn = (b < 15) ? *(const float4*)(xb + (b + 1) * XSTRIDE) : xc;
            A0[b] = fmaf(c0.x, xc.x, fmaf(c0.y, xc.y, fmaf(c0.z, xc.z, fmaf(c0.w, xc.w, A0[b]))));
            A1[b] = fmaf(c1.x, xc.x, fmaf(c1.y, xc.y, fmaf(c1.z, xc.z, fmaf(c1.w, xc.w, A1[b]))));
            xc = xn;
        }
        c0 = n0; c1 = n1;
    }
}

// mel/gate projection for timestep tq (blocks 128..147)
__device__ void write_outputs(const Params& P, int tq) {
    const int w = threadIdx.x >> 5, lane = threadIdx.x & 31;
    int gw = ((int)blockIdx.x - 128) * 16 + w;   // 0..79 mel rows, 80 gate
    if (gw > 80) return;
    const float* wr = (gw < 80) ? (P.Wproj + gw * (NH + NENC)) : P.Wgate;
    float bias = (gw < 80) ? P.bproj[gw] : P.bgate[0];
    const float4* wr4 = (const float4*)wr;
    const float4* dh4 = (const float4*)g_dh;
    const float4* cx4 = (const float4*)g_ctx;
    float acc[16];
#pragma unroll
    for (int b = 0; b < 16; ++b) acc[b] = 0.f;
    for (int k = lane; k < NH / 4; k += 32) {
        float4 wv = wr4[k];
#pragma unroll
        for (int b = 0; b < 16; ++b) {
            float4 x = dh4[b * 256 + k];
            acc[b] = fmaf(wv.x, x.x, fmaf(wv.y, x.y, fmaf(wv.z, x.z, fmaf(wv.w, x.w, acc[b]))));
        }
    }
    for (int k = lane; k < NENC / 4; k += 32) {
        float4 wv = wr4[256 + k];
#pragma unroll
        for (int b = 0; b < 16; ++b) {
            float4 x = cx4[b * 128 + k];
            acc[b] = fmaf(wv.x, x.x, fmaf(wv.y, x.y, fmaf(wv.z, x.z, fmaf(wv.w, x.w, acc[b]))));
        }
    }
    wred16(acc);
    if (lane < 16) {
        float val = pick16(acc, lane) + bias;
        if (gw < 80) P.out_mel[(lane * NMEL + gw) * NT + tq] = val;
        else         P.out_gate[lane * NT + tq] = val;
    }
}

__global__ void __launch_bounds__(TPB) decoder_kernel(Params P) {
    extern __shared__ float smf[];
    const int blk = blockIdx.x, tid = threadIdx.x;
    const int w = tid >> 5, lane = tid & 31;
    const int h = tid >> 8, lt = tid & 255;   // half-block split for prelude

    // ---------- prelude: zero state ----------
    {
        const int g0 = blk * TPB + tid, gs = GRID * TPB;
        for (int i = g0; i < NB * NH; i += gs) {
            g_ah[0][i] = 0.f; g_ah[1][i] = 0.f;
            g_ac[i] = 0.f; g_dh[i] = 0.f; g_dc[i] = 0.f;
        }
        for (int i = g0; i < NB * NS; i += gs) { g_aw[i] = 0.f; g_awc[i] = 0.f; }
        for (int i = g0; i < NB * NENC; i += gs) g_ctx[i] = 0.f;
        for (int i = g0; i < NB * NPRE; i += gs) g_xs[i] = 0.f;  // xs[0] = prenet(0) = 0
    }
    // prenet for t=1..399 (each half-block processes its own (t,b) pair)
    {
        float* sx = smf + h * 96;          // 80 each
        float* sh1 = smf + 192 + h * 256;  // 256 each
        const int NP = (NT - 1) * NB;
        const int KMAX = (NP + 2 * GRID - 1) / (2 * GRID);
        for (int k = 0; k < KMAX; ++k) {
            int pi = blk * 2 + h + k * 2 * GRID;
            bool act = pi < NP;
            int tt = act ? pi / NB + 1 : 1, b = act ? pi % NB : 0;
            if (act && lt < NMEL) sx[lt] = P.dec_in[(b * NMEL + lt) * NT + (tt - 1)];
            __syncthreads();
            float a1v = 0.f;
            if (act) {
                const float* w1 = P.Wpre1 + lt * NMEL;
#pragma unroll 4
                for (int kk = 0; kk < NMEL; ++kk) a1v += w1[kk] * sx[kk];
                sh1[lt] = fmaxf(a1v, 0.f);
            }
            __syncthreads();
            if (act) {
                const float4* w2 = (const float4*)(P.Wpre2 + lt * NPRE);
                const float4* h4 = (const float4*)sh1;
                float a = 0.f;
#pragma unroll 8
                for (int kk = 0; kk < NPRE / 4; ++kk) {
                    float4 wv = w2[kk], x = h4[kk];
                    a = fmaf(wv.x, x.x, fmaf(wv.y, x.y, fmaf(wv.z, x.z, fmaf(wv.w, x.w, a))));
                }
                g_xs[(tt * NB + b) * NPRE + lt] = fmaxf(a, 0.f);
            }
            __syncthreads();
        }
    }
    // processed memory pm[b][s][a]
    {
        float* srow = smf + h * 512;  // 512 each
        const int NR = NB * NS;
        const int RMAX = (NR + 2 * GRID - 1) / (2 * GRID);
        const int wl = w & 7;
        for (int k = 0; k < RMAX; ++k) {
            int r = blk * 2 + h + k * 2 * GRID;
            bool act = r < NR;
            __syncthreads();
            if (act) for (int i = lt; i < NENC; i += 256) srow[i] = P.memory[(size_t)r * NENC + i];
            __syncthreads();
            if (act) {
                const float4* sr4 = (const float4*)srow;
                for (int a = wl; a < NATT; a += 8) {
                    const float4* wm = (const float4*)(P.Wm + a * NENC);
                    float acc = 0.f;
#pragma unroll
                    for (int kk = lane; kk < NENC / 4; kk += 32) {
                        float4 wv = wm[kk], x = sr4[kk];
                        acc = fmaf(wv.x, x.x, fmaf(wv.y, x.y, fmaf(wv.z, x.z, fmaf(wv.w, x.w, acc))));
                    }
#pragma unroll
                    for (int off = 16; off > 0; off >>= 1)
                        acc += __shfl_xor_sync(0xffffffffu, acc, off);
                    if (lane == 0) g_pm[(size_t)r * NATT + a] = acc;
                }
            }
        }
    }
    grid_sync();

    int p = 0;

    for (int t = 0; t < NT; ++t) {
        float D0[16], D1[16];  // decoder partial accs (live phase2 -> phase3)

        // ================= PHASE 1: attention LSTM =================
        if (blk < 128) {
            float* sA = smf;                        // [16][768] = [x|ctx]
            float* sH = smf + NB * 768;             // [16][1024] = ah_prev
            float* zb = smf + NB * 768 + NB * NH;   // [4][8][16] gate z values
            {
                float4* sA4 = (float4*)sA;
                const float4* xs4 = (const float4*)(g_xs + (size_t)t * NB * NPRE);
                for (int i = tid; i < NB * NPRE / 4; i += TPB)
                    sA4[(i >> 6) * 192 + (i & 63)] = xs4[i];
                const float4* cx4 = (const float4*)g_ctx;
                for (int i = tid; i < NB * NENC / 4; i += TPB)
                    sA4[(i >> 7) * 192 + 64 + (i & 127)] = cx4[i];
                float4* sH4 = (float4*)sH;
                const float4* ah4 = (const float4*)g_ah[p];
                for (int i = tid; i < NB * NH / 4; i += TPB) sH4[i] = ah4[i];
            }
            __syncthreads();

            const int ul = w >> 1, gA = (w & 1) * 2;   // unit-in-block, first gate row
            const int u = blk * 8 + ul;
            float A0[16], A1[16];
#pragma unroll
            for (int b = 0; b < 16; ++b) { A0[b] = A1[b] = 0.f; }
            gemm2_accum<768, 6>((const float4*)(P.Wih_a + (size_t)(gA * NH + u) * 768),
                                (const float4*)(P.Wih_a + (size_t)((gA + 1) * NH + u) * 768),
                                sA, lane, A0, A1);
            gemm2_accum<NH, 8>((const float4*)(P.Whh_a + (size_t)(gA * NH + u) * NH),
                               (const float4*)(P.Whh_a + (size_t)((gA + 1) * NH + u) * NH),
                               sH, lane, A0, A1);
            wred16(A0); wred16(A1);
            if (lane < 16) {
                zb[gA * 128 + ul * 16 + lane] = pick16(A0, lane);
                zb[(gA + 1) * 128 + ul * 16 + lane] = pick16(A1, lane);
            }
            __syncthreads();
            if (tid < 128) {
                const int ul2 = tid >> 4, b = tid & 15;
                const int uu = blk * 8 + ul2;
                float zi = zb[ul2 * 16 + b]          + P.bih_a[uu]          + P.bhh_a[uu];
                float zf = zb[128 + ul2 * 16 + b]    + P.bih_a[NH + uu]     + P.bhh_a[NH + uu];
                float zg = zb[256 + ul2 * 16 + b]    + P.bih_a[2 * NH + uu] + P.bhh_a[2 * NH + uu];
                float zo = zb[384 + ul2 * 16 + b]    + P.bih_a[3 * NH + uu] + P.bhh_a[3 * NH + uu];
                float c = sigf(zf) * g_ac[b * NH + uu] + sigf(zi) * tanhf(zg);
                g_ac[b * NH + uu] = c;
                g_ah[p ^ 1][b * NH + uu] = sigf(zo) * tanhf(c);
            }
        } else if (t > 0) {
            write_outputs(P, t - 1);
        }
        grid_sync();
        p ^= 1;  // g_ah[p] = new ah

        // ================= PHASE 2 =================
        if (blk < 16) {
            // full attention for batch b = blk
            const int b = blk;
            float* s_aw = smf;             // 256
            float* s_awc = smf + 256;      // 256
            float* s_q = smf + 512;        // 128
            float* s_e = smf + 640;        // 256
            float* s_red = smf + 896;      // 32
            float* s_loc = smf + 1024;     // [s][f] 8192
            float* s_wldT = smf + 9216;    // [f][a] 4096
            float* s_v = smf + 13312;      // 128
            float* s_ah = smf + 13440;     // 1024
            if (tid < 256) {
                s_aw[tid] = g_aw[b * NS + tid];
                s_awc[tid] = g_awc[b * NS + tid];
            }
            for (int i = tid; i < NATT * NFILT; i += TPB)
                s_wldT[(i & 31) * NATT + (i >> 5)] = P.Wld[i];  // i = a*32+f
            if (tid < NATT) s_v[tid] = P.v[tid];
            {
                float4* sa4 = (float4*)s_ah;
                const float4* ah4 = (const float4*)(g_ah[p] + b * NH);
                if (tid < NH / 4) sa4[tid] = ah4[tid];
            }
            __syncthreads();
            // q = ah_new[b] @ Wq^T : 16 warps x 8 rows
            const float4* ah4 = (const float4*)s_ah;
            for (int a = w * 8; a < w * 8 + 8; ++a) {
                const float4* wq = (const float4*)(P.Wq + (size_t)a * NH);
                float acc = 0.f;
#pragma unroll
                for (int k = lane; k < NH / 4; k += 32) {
                    float4 wv = wq[k], x = ah4[k];
                    acc = fmaf(wv.x, x.x, fmaf(wv.y, x.y, fmaf(wv.z, x.z, fmaf(wv.w, x.w, acc))));
                }
#pragma unroll
                for (int off = 16; off > 0; off >>= 1)
                    acc += __shfl_xor_sync(0xffffffffu, acc, off);
                if (lane == 0) s_q[a] = acc;
            }
            // location conv (pad 15)
            for (int idx = tid; idx < NFILT * NS; idx += TPB) {
                int f = idx & 31, s = idx >> 5;
                const float* w0 = P.Wc + f * (2 * KC);
                const float* w1 = w0 + KC;
                float acc = 0.f;
#pragma unroll
                for (int kk = 0; kk < KC; ++kk) {
                    int ss = s + kk - (KC / 2);
                    if (ss >= 0 && ss < NS)
                        acc += w0[kk] * s_aw[ss] + w1[kk] * s_awc[ss];
                }
                s_loc[s * 32 + f] = acc;
            }
            __syncthreads();
            // energies : 16 warps x 16 s
            const int ml = P.mlen[b];
            for (int s = w * 16; s < w * 16 + 16; ++s) {
                float part = 0.f;
#pragma unroll
                for (int aa = 0; aa < 4; ++aa) {
                    int a = lane + aa * 32;
                    float pa = 0.f;
#pragma unroll
                    for (int f = 0; f < NFILT; ++f) pa += s_wldT[f * NATT + a] * s_loc[s * 32 + f];
                    part += s_v[a] * tanhf(s_q[a] + pa + g_pm[(size_t)(b * NS + s) * NATT + a]);
                }
#pragma unroll
                for (int off = 16; off > 0; off >>= 1)
                    part += __shfl_xor_sync(0xffffffffu, part, off);
                if (lane == 0) s_e[s] = (s < ml) ? part : -1e9f;
            }
            __syncthreads();
            // softmax over S (first 256 threads; syncs unconditional)
            float val = 0.f, ex = 0.f;
            if (tid < 256) {
                val = s_e[tid];
                float m = val;
#pragma unroll
                for (int off = 16; off > 0; off >>= 1)
                    m = fmaxf(m, __shfl_xor_sync(0xffffffffu, m, off));
                if (lane == 0) s_red[w] = m;
            }
            __syncthreads();
            if (tid == 0) {
                float mm = s_red[0];
                for (int i = 1; i < 8; ++i) mm = fmaxf(mm, s_red[i]);
                s_red[8] = mm;
            }
            __syncthreads();
            if (tid < 256) {
                ex = expf(val - s_red[8]);
                float sv = ex;
#pragma unroll
                for (int off = 16; off > 0; off >>= 1)
                    sv += __shfl_xor_sync(0xffffffffu, sv, off);
                if (lane == 0) s_red[16 + w] = sv;
            }
            __syncthreads();
            if (tid == 0) {
                float ss = 0.f;
                for (int i = 0; i < 8; ++i) ss += s_red[16 + i];
                s_red[24] = ss;
            }
            __syncthreads();
            if (tid < 256) {
                float awn = ex / s_red[24];
                s_aw[tid] = awn;
                g_aw[b * NS + tid] = awn;
                g_awc[b * NS + tid] = s_awc[tid] + awn;
                P.out_align[((size_t)b * NT + t) * NS + tid] = awn;
            }
            __syncthreads();
            // ctx = aw @ memory[b] : one thread per enc dim (512)
            {
                const float* mem_b = P.memory + (size_t)b * NS * NENC;
                float a0 = 0.f;
#pragma unroll 8
                for (int s = 0; s < NS; ++s)
                    a0 = fmaf(s_aw[s], mem_b[s * NENC + tid], a0);
                g_ctx[b * NENC + tid] = a0;
            }
        } else if (blk < 144) {
            // decoder-LSTM partial: ah part + dh part (accs live across barrier)
            float* sAh = smf;             // [16][1024]
            float* sDh = smf + NB * NH;   // [16][1024]
            {
                float4* a4 = (float4*)sAh;
                float4* d4 = (float4*)sDh;
                const float4* ga4 = (const float4*)g_ah[p];
                const float4* gd4 = (const float4*)g_dh;
                for (int i = tid; i < NB * NH / 4; i += TPB) { a4[i] = ga4[i]; d4[i] = gd4[i]; }
            }
            __syncthreads();
            const int ul = w >> 1, gA = (w & 1) * 2;
            const int u = (blk - 16) * 8 + ul;
#pragma unroll
            for (int b = 0; b < 16; ++b) { D0[b] = D1[b] = 0.f; }
            gemm2_accum<NH, 8>((const float4*)(P.Wih_d + (size_t)(gA * NH + u) * 1536),
                               (const float4*)(P.Wih_d + (size_t)((gA + 1) * NH + u) * 1536),
                               sAh, lane, D0, D1);
            gemm2_accum<NH, 8>((const float4*)(P.Whh_d + (size_t)(gA * NH + u) * NH),
                               (const float4*)(P.Whh_d + (size_t)((gA + 1) * NH + u) * NH),
                               sDh, lane, D0, D1);
        }
        grid_sync();

        // ================= PHASE 3: finish decoder LSTM with new ctx =================
        if (blk >= 16 && blk < 144) {
            float* sC = smf;               // [16][512]
            float* zb = smf + NB * NENC;   // [4][8][16]
            {
                float4* c4 = (float4*)sC;
                const float4* gc4 = (const float4*)g_ctx;
                for (int i = tid; i < NB * NENC / 4; i += TPB) c4[i] = gc4[i];
            }
            __syncthreads();
            const int ul = w >> 1, gA = (w & 1) * 2;
            const int u = (blk - 16) * 8 + ul;
            gemm2_accum<NENC, 4>((const float4*)(P.Wih_d + (size_t)(gA * NH + u) * 1536 + NH),
                                 (const float4*)(P.Wih_d + (size_t)((gA + 1) * NH + u) * 1536 + NH),
                                 sC, lane, D0, D1);
            wred16(D0); wred16(D1);
            if (lane < 16) {
                zb[gA * 128 + ul * 16 + lane] = pick16(D0, lane);
                zb[(gA + 1) * 128 + ul * 16 + lane] = pick16(D1, lane);
            }
            __syncthreads();
            if (tid < 128) {
                const int ul2 = tid >> 4, b = tid & 15;
                const int uu = (blk - 16) * 8 + ul2;
                float zi = zb[ul2 * 16 + b]       + P.bih_d[uu]          + P.bhh_d[uu];
                float zf = zb[128 + ul2 * 16 + b] + P.bih_d[NH + uu]     + P.bhh_d[NH + uu];
                float zg = zb[256 + ul2 * 16 + b] + P.bih_d[2 * NH + uu] + P.bhh_d[2 * NH + uu];
                float zo = zb[384 + ul2 * 16 + b] + P.bih_d[3 * NH + uu] + P.bhh_d[3 * NH + uu];
                float c = sigf(zf) * g_dc[b * NH + uu] + sigf(zi) * tanhf(zg);
                g_dc[b * NH + uu] = c;
                g_dh[b * NH + uu] = sigf(zo) * tanhf(c);
            }
        }
        grid_sync();
    }

    // final timestep outputs
    if (blk >= 128) write_outputs(P, NT - 1);
}

extern "C" void kernel_launch(void* const* d_in, const int* in_sizes, int n_in,
                              void* d_out, int out_size) {
    Params P;
    P.memory = (const float*)d_in[0];
    P.dec_in = (const float*)d_in[1];
    P.Wpre1  = (const float*)d_in[2];
    P.Wpre2  = (const float*)d_in[3];
    P.Wih_a  = (const float*)d_in[4];
    P.Whh_a  = (const float*)d_in[5];
    P.bih_a  = (const float*)d_in[6];
    P.bhh_a  = (const float*)d_in[7];
    P.Wq     = (const float*)d_in[8];
    P.Wm     = (const float*)d_in[9];
    P.v      = (const float*)d_in[10];
    P.Wc     = (const float*)d_in[11];
    P.Wld    = (const float*)d_in[12];
    P.Wih_d  = (const float*)d_in[13];
    P.Whh_d  = (const float*)d_in[14];
    P.bih_d  = (const float*)d_in[15];
    P.bhh_d  = (const float*)d_in[16];
    P.Wproj  = (const float*)d_in[17];
    P.bproj  = (const float*)d_in[18];
    P.Wgate  = (const float*)d_in[19];
    P.bgate  = (const float*)d_in[20];
    P.mlen   = (const int*)d_in[21];
    float* out = (float*)d_out;
    P.out_mel   = out;
    P.out_gate  = out + NB * NMEL * NT;
    P.out_align = out + NB * NMEL * NT + NB * NT;

    cudaFuncSetAttribute(decoder_kernel, cudaFuncAttributeMaxDynamicSharedMemorySize, SMEM_BYTES);
    decoder_kernel<<<GRID, TPB, SMEM_BYTES>>>(P);
}

// round 13
// speedup vs baseline: 2.0987x; 2.0987x over previous
#include <cuda_runtime.h>

#define NB 16
#define NS 256
#define NT 400
#define NMEL 80
#define NPRE 256
#define NENC 512
#define NH 1024
#define NATT 128
#define NFILT 32
#define KC 31
#define GRID 148
#define TPB 512
#define SMEM_BYTES 131072

struct Params {
    const float *memory, *dec_in, *Wpre1, *Wpre2, *Wih_a, *Whh_a, *bih_a, *bhh_a;
    const float *Wq, *Wm, *v, *Wc, *Wld, *Wih_d, *Whh_d, *bih_d, *bhh_d;
    const float *Wproj, *bproj, *Wgate, *bgate;
    const int* mlen;
    float *out_mel, *out_gate, *out_align;
};

__device__ float g_xs[NT * NB * NPRE];
__device__ float g_pm[NB * NS * NATT];
__device__ float g_ah[2][NB * NH];
__device__ float g_ac[NB * NH];
__device__ float g_dh[NB * NH];
__device__ float g_dc[NB * NH];
__device__ float g_aw[NB * NS];
__device__ float g_awc[NB * NS];
__device__ float g_ctx[NB * NENC];
__device__ unsigned g_cnt = 0;
__device__ unsigned g_gen = 0;

// CG-style barrier: syncthreads + elected-thread release-atomic / acquire-spin.
// No per-thread membar.gpu (avoids the fence storm + potential L1 flushes).
__device__ __forceinline__ void grid_sync() {
    __syncthreads();
    if (threadIdx.x == 0) {
        unsigned gen = g_gen;
        unsigned prev;
        asm volatile("atom.add.release.gpu.u32 %0, [%1], %2;"
                     : "=r"(prev) : "l"(&g_cnt), "r"(1u) : "memory");
        if (prev == GRID - 1) {
            g_cnt = 0;
            asm volatile("st.release.gpu.u32 [%0], %1;"
                         :: "l"(&g_gen), "r"(gen + 1) : "memory");
        } else {
            unsigned cur;
            do {
                asm volatile("ld.acquire.gpu.u32 %0, [%1];"
                             : "=r"(cur) : "l"(&g_gen) : "memory");
            } while (cur == gen);
        }
    }
    __syncthreads();
}

__device__ __forceinline__ float sigf(float x) { return 1.0f / (1.0f + __expf(-x)); }

__device__ __forceinline__ void wred16(float* a) {
#pragma unroll
    for (int off = 16; off > 0; off >>= 1)
#pragma unroll
        for (int i = 0; i < 16; ++i)
            a[i] += __shfl_xor_sync(0xffffffffu, a[i], off);
}

__device__ __forceinline__ float pick16(const float* a, int lane) {
    float v = a[0];
#pragma unroll
    for (int b = 1; b < 16; ++b)
        if (lane == b) v = a[b];
    return v;
}

// 2-gate-row x 16-batch GEMM accumulation over NCH chunks of 128 k's.
template <int XSTRIDE, int NCH>
__device__ __forceinline__ void gemm2_accum(
    const float4* __restrict__ W0, const float4* __restrict__ W1,
    const float* __restrict__ sX, int lane,
    float* A0, float* A1)
{
    float4 c0 = W0[lane], c1 = W1[lane];
#pragma unroll
    for (int c = 0; c < NCH; ++c) {
        const int nidx = ((c + 1 < NCH) ? (c + 1) : c) * 32 + lane;
        float4 n0 = W0[nidx], n1 = W1[nidx];
        const float* xb = sX + c * 128 + lane * 4;
        float4 xc = *(const float4*)(xb);
#pragma unroll
        for (int b = 0; b < 16; ++b) {
            float4 xn = (b < 15) ? *(const float4*)(xb + (b + 1) * XSTRIDE) : xc;
            A0[b] = fmaf(c0.x, xc.x, fmaf(c0.y, xc.y, fmaf(c0.z, xc.z, fmaf(c0.w, xc.w, A0[b]))));
            A1[b] = fmaf(c1.x, xc.x, fmaf(c1.y, xc.y, fmaf(c1.z, xc.z, fmaf(c1.w, xc.w, A1[b]))));
            xc = xn;
        }
        c0 = n0; c1 = n1;
    }
}

// mel/gate projection for timestep tq (blocks 128..147)
__device__ void write_outputs(const Params& P, int tq) {
    const int w = threadIdx.x >> 5, lane = threadIdx.x & 31;
    int gw = ((int)blockIdx.x - 128) * 16 + w;   // 0..79 mel rows, 80 gate
    if (gw > 80) return;
    const float* wr = (gw < 80) ? (P.Wproj + gw * (NH + NENC)) : P.Wgate;
    float bias = (gw < 80) ? P.bproj[gw] : P.bgate[0];
    const float4* wr4 = (const float4*)wr;
    const float4* dh4 = (const float4*)g_dh;
    const float4* cx4 = (const float4*)g_ctx;
    float acc[16];
#pragma unroll
    for (int b = 0; b < 16; ++b) acc[b] = 0.f;
    for (int k = lane; k < NH / 4; k += 32) {
        float4 wv = wr4[k];
#pragma unroll
        for (int b = 0; b < 16; ++b) {
            float4 x = dh4[b * 256 + k];
            acc[b] = fmaf(wv.x, x.x, fmaf(wv.y, x.y, fmaf(wv.z, x.z, fmaf(wv.w, x.w, acc[b]))));
        }
    }
    for (int k = lane; k < NENC / 4; k += 32) {
        float4 wv = wr4[256 + k];
#pragma unroll
        for (int b = 0; b < 16; ++b) {
            float4 x = cx4[b * 128 + k];
            acc[b] = fmaf(wv.x, x.x, fmaf(wv.y, x.y, fmaf(wv.z, x.z, fmaf(wv.w, x.w, acc[b]))));
        }
    }
    wred16(acc);
    if (lane < 16) {
        float val = pick16(acc, lane) + bias;
        if (gw < 80) P.out_mel[(lane * NMEL + gw) * NT + tq] = val;
        else         P.out_gate[lane * NT + tq] = val;
    }
}

__global__ void __launch_bounds__(TPB) decoder_kernel(Params P) {
    extern __shared__ float smf[];
    const int blk = blockIdx.x, tid = threadIdx.x;
    const int w = tid >> 5, lane = tid & 31;
    const int h = tid >> 8, lt = tid & 255;   // half-block split for prelude

    // ---------- prelude: zero state ----------
    {
        const int g0 = blk * TPB + tid, gs = GRID * TPB;
        for (int i = g0; i < NB * NH; i += gs) {
            g_ah[0][i] = 0.f; g_ah[1][i] = 0.f;
            g_ac[i] = 0.f; g_dh[i] = 0.f; g_dc[i] = 0.f;
        }
        for (int i = g0; i < NB * NS; i += gs) { g_aw[i] = 0.f; g_awc[i] = 0.f; }
        for (int i = g0; i < NB * NENC; i += gs) g_ctx[i] = 0.f;
        for (int i = g0; i < NB * NPRE; i += gs) g_xs[i] = 0.f;  // xs[0] = prenet(0) = 0
    }
    // prenet for t=1..399 (each half-block processes its own (t,b) pair)
    {
        float* sx = smf + h * 96;          // 80 each
        float* sh1 = smf + 192 + h * 256;  // 256 each
        const int NP = (NT - 1) * NB;
        const int KMAX = (NP + 2 * GRID - 1) / (2 * GRID);
        for (int k = 0; k < KMAX; ++k) {
            int pi = blk * 2 + h + k * 2 * GRID;
            bool act = pi < NP;
            int tt = act ? pi / NB + 1 : 1, b = act ? pi % NB : 0;
            if (act && lt < NMEL) sx[lt] = P.dec_in[(b * NMEL + lt) * NT + (tt - 1)];
            __syncthreads();
            float a1v = 0.f;
            if (act) {
                const float* w1 = P.Wpre1 + lt * NMEL;
#pragma unroll 4
                for (int kk = 0; kk < NMEL; ++kk) a1v += w1[kk] * sx[kk];
                sh1[lt] = fmaxf(a1v, 0.f);
            }
            __syncthreads();
            if (act) {
                const float4* w2 = (const float4*)(P.Wpre2 + lt * NPRE);
                const float4* h4 = (const float4*)sh1;
                float a = 0.f;
#pragma unroll 8
                for (int kk = 0; kk < NPRE / 4; ++kk) {
                    float4 wv = w2[kk], x = h4[kk];
                    a = fmaf(wv.x, x.x, fmaf(wv.y, x.y, fmaf(wv.z, x.z, fmaf(wv.w, x.w, a))));
                }
                g_xs[(tt * NB + b) * NPRE + lt] = fmaxf(a, 0.f);
            }
            __syncthreads();
        }
    }
    // processed memory pm[b][s][a]
    {
        float* srow = smf + h * 512;  // 512 each
        const int NR = NB * NS;
        const int RMAX = (NR + 2 * GRID - 1) / (2 * GRID);
        const int wl = w & 7;
        for (int k = 0; k < RMAX; ++k) {
            int r = blk * 2 + h + k * 2 * GRID;
            bool act = r < NR;
            __syncthreads();
            if (act) for (int i = lt; i < NENC; i += 256) srow[i] = P.memory[(size_t)r * NENC + i];
            __syncthreads();
            if (act) {
                const float4* sr4 = (const float4*)srow;
                for (int a = wl; a < NATT; a += 8) {
                    const float4* wm = (const float4*)(P.Wm + a * NENC);
                    float acc = 0.f;
#pragma unroll
                    for (int kk = lane; kk < NENC / 4; kk += 32) {
                        float4 wv = wm[kk], x = sr4[kk];
                        acc = fmaf(wv.x, x.x, fmaf(wv.y, x.y, fmaf(wv.z, x.z, fmaf(wv.w, x.w, acc))));
                    }
#pragma unroll
                    for (int off = 16; off > 0; off >>= 1)
                        acc += __shfl_xor_sync(0xffffffffu, acc, off);
                    if (lane == 0) g_pm[(size_t)r * NATT + a] = acc;
                }
            }
        }
    }
    grid_sync();

    int p = 0;

    for (int t = 0; t < NT; ++t) {
        float D0[16], D1[16];  // decoder partial accs (live phase2 -> phase3)

        // ================= PHASE 1: attention LSTM =================
        if (blk < 128) {
            float* sA = smf;                        // [16][768] = [x|ctx]
            float* sH = smf + NB * 768;             // [16][1024] = ah_prev
            float* zb = smf + NB * 768 + NB * NH;   // [4][8][16] gate z values
            {
                float4* sA4 = (float4*)sA;
                const float4* xs4 = (const float4*)(g_xs + (size_t)t * NB * NPRE);
                for (int i = tid; i < NB * NPRE / 4; i += TPB)
                    sA4[(i >> 6) * 192 + (i & 63)] = xs4[i];
                const float4* cx4 = (const float4*)g_ctx;
                for (int i = tid; i < NB * NENC / 4; i += TPB)
                    sA4[(i >> 7) * 192 + 64 + (i & 127)] = cx4[i];
                float4* sH4 = (float4*)sH;
                const float4* ah4 = (const float4*)g_ah[p];
                for (int i = tid; i < NB * NH / 4; i += TPB) sH4[i] = ah4[i];
            }
            __syncthreads();

            const int ul = w >> 1, gA = (w & 1) * 2;   // unit-in-block, first gate row
            const int u = blk * 8 + ul;
            float A0[16], A1[16];
#pragma unroll
            for (int b = 0; b < 16; ++b) { A0[b] = A1[b] = 0.f; }
            gemm2_accum<768, 6>((const float4*)(P.Wih_a + (size_t)(gA * NH + u) * 768),
                                (const float4*)(P.Wih_a + (size_t)((gA + 1) * NH + u) * 768),
                                sA, lane, A0, A1);
            gemm2_accum<NH, 8>((const float4*)(P.Whh_a + (size_t)(gA * NH + u) * NH),
                               (const float4*)(P.Whh_a + (size_t)((gA + 1) * NH + u) * NH),
                               sH, lane, A0, A1);
            wred16(A0); wred16(A1);
            if (lane < 16) {
                zb[gA * 128 + ul * 16 + lane] = pick16(A0, lane);
                zb[(gA + 1) * 128 + ul * 16 + lane] = pick16(A1, lane);
            }
            __syncthreads();
            if (tid < 128) {
                const int ul2 = tid >> 4, b = tid & 15;
                const int uu = blk * 8 + ul2;
                float zi = zb[ul2 * 16 + b]          + P.bih_a[uu]          + P.bhh_a[uu];
                float zf = zb[128 + ul2 * 16 + b]    + P.bih_a[NH + uu]     + P.bhh_a[NH + uu];
                float zg = zb[256 + ul2 * 16 + b]    + P.bih_a[2 * NH + uu] + P.bhh_a[2 * NH + uu];
                float zo = zb[384 + ul2 * 16 + b]    + P.bih_a[3 * NH + uu] + P.bhh_a[3 * NH + uu];
                float c = sigf(zf) * g_ac[b * NH + uu] + sigf(zi) * tanhf(zg);
                g_ac[b * NH + uu] = c;
                g_ah[p ^ 1][b * NH + uu] = sigf(zo) * tanhf(c);
            }
        } else if (t > 0) {
            write_outputs(P, t - 1);
        }
        grid_sync();
        p ^= 1;  // g_ah[p] = new ah

        // ================= PHASE 2 =================
        if (blk < 16) {
            // full attention for batch b = blk
            const int b = blk;
            float* s_aw = smf;             // 256
            float* s_awc = smf + 256;      // 256
            float* s_q = smf + 512;        // 128
            float* s_e = smf + 640;        // 256
            float* s_red = smf + 896;      // 32
            float* s_loc = smf + 1024;     // [s][f] 8192
            float* s_wldT = smf + 9216;    // [f][a] 4096
            float* s_v = smf + 13312;      // 128
            float* s_ah = smf + 13440;     // 1024
            float* s_awp = smf + 14464;    // 288 (aw zero-padded by 15)
            float* s_awcp = smf + 14752;   // 288
            float* s_wcT = smf + 15040;    // [kk][ch][f] 1984
            if (tid < 256) {
                s_aw[tid] = g_aw[b * NS + tid];
                s_awc[tid] = g_awc[b * NS + tid];
            }
            if (tid < 288) {
                bool in = (tid >= 15 && tid < 271);
                s_awp[tid]  = in ? g_aw[b * NS + tid - 15] : 0.f;
                s_awcp[tid] = in ? g_awc[b * NS + tid - 15] : 0.f;
            }
            for (int i = tid; i < NATT * NFILT; i += TPB)
                s_wldT[(i & 31) * NATT + (i >> 5)] = P.Wld[i];  // i = a*32+f -> [f][a]
            for (int i = tid; i < NFILT * 2 * KC; i += TPB) {
                int f = i / (2 * KC), r = i % (2 * KC), ch = r / KC, kk = r % KC;
                s_wcT[(kk * 2 + ch) * 32 + f] = P.Wc[i];
            }
            if (tid < NATT) s_v[tid] = P.v[tid];
            {
                float4* sa4 = (float4*)s_ah;
                const float4* ah4 = (const float4*)(g_ah[p] + b * NH);
                if (tid < NH / 4) sa4[tid] = ah4[tid];
            }
            __syncthreads();
            // q = ah_new[b] @ Wq^T : 16 warps x 8 rows
            const float4* ah4 = (const float4*)s_ah;
            for (int a = w * 8; a < w * 8 + 8; ++a) {
                const float4* wq = (const float4*)(P.Wq + (size_t)a * NH);
                float acc = 0.f;
#pragma unroll
                for (int k = lane; k < NH / 4; k += 32) {
                    float4 wv = wq[k], x = ah4[k];
                    acc = fmaf(wv.x, x.x, fmaf(wv.y, x.y, fmaf(wv.z, x.z, fmaf(wv.w, x.w, acc))));
                }
#pragma unroll
                for (int off = 16; off > 0; off >>= 1)
                    acc += __shfl_xor_sync(0xffffffffu, acc, off);
                if (lane == 0) s_q[a] = acc;
            }
            __syncthreads();
            // location conv: warp w covers s in [w*16, w*16+16), lane = filter f.
            // Sliding 16-register ring over padded aw/awc; conflict-free Wc LDS.
            {
                const int sb = w * 16;
                float acc[16];
#pragma unroll
                for (int j = 0; j < 16; ++j) acc[j] = 0.f;
                float ring[16];
#pragma unroll
                for (int j = 0; j < 16; ++j) ring[j] = s_awp[sb + j];
#pragma unroll
                for (int k = 0; k < KC; ++k) {
                    float wk = s_wcT[(k * 2 + 0) * 32 + lane];
#pragma unroll
                    for (int j = 0; j < 16; ++j)
                        acc[j] = fmaf(wk, ring[(k + j) & 15], acc[j]);
                    ring[k & 15] = s_awp[sb + k + 16];
                }
#pragma unroll
                for (int j = 0; j < 16; ++j) ring[j] = s_awcp[sb + j];
#pragma unroll
                for (int k = 0; k < KC; ++k) {
                    float wk = s_wcT[(k * 2 + 1) * 32 + lane];
#pragma unroll
                    for (int j = 0; j < 16; ++j)
                        acc[j] = fmaf(wk, ring[(k + j) & 15], acc[j]);
                    ring[k & 15] = s_awcp[sb + k + 16];
                }
#pragma unroll
                for (int j = 0; j < 16; ++j) s_loc[(sb + j) * 32 + lane] = acc[j];
            }
            __syncthreads();
            // energies: register-tiled GEMM. warp w: s in [w*16,w*16+16),
            // lane covers a = lane + 32*aa, aa=0..3. acc init = q[a] + pm[s][a].
            {
                const int sb = w * 16;
                const int ml = P.mlen[b];
                float acc0[16], acc1[16], acc2[16], acc3[16];
                const float* pmb = g_pm + ((size_t)b * NS + sb) * NATT;
                float q0 = s_q[lane], q1 = s_q[lane + 32], q2 = s_q[lane + 64], q3 = s_q[lane + 96];
#pragma unroll
                for (int j = 0; j < 16; ++j) {
                    const float* pr = pmb + j * NATT;
                    acc0[j] = q0 + pr[lane];
                    acc1[j] = q1 + pr[lane + 32];
                    acc2[j] = q2 + pr[lane + 64];
                    acc3[j] = q3 + pr[lane + 96];
                }
#pragma unroll 4
                for (int f = 0; f < NFILT; ++f) {
                    float w0 = s_wldT[f * NATT + lane];
                    float w1 = s_wldT[f * NATT + lane + 32];
                    float w2 = s_wldT[f * NATT + lane + 64];
                    float w3 = s_wldT[f * NATT + lane + 96];
#pragma unroll
                    for (int j = 0; j < 16; ++j) {
                        float lv = s_loc[(sb + j) * 32 + f];
                        acc0[j] = fmaf(w0, lv, acc0[j]);
                        acc1[j] = fmaf(w1, lv, acc1[j]);
                        acc2[j] = fmaf(w2, lv, acc2[j]);
                        acc3[j] = fmaf(w3, lv, acc3[j]);
                    }
                }
                float v0 = s_v[lane], v1 = s_v[lane + 32], v2 = s_v[lane + 64], v3 = s_v[lane + 96];
                float es[16];
#pragma unroll
                for (int j = 0; j < 16; ++j) {
                    es[j] = v0 * tanhf(acc0[j]) + v1 * tanhf(acc1[j])
                          + v2 * tanhf(acc2[j]) + v3 * tanhf(acc3[j]);
                }
                wred16(es);
                if (lane < 16) {
                    int s = sb + lane;
                    s_e[s] = (s < ml) ? pick16(es, lane) : -1e9f;
                }
            }
            __syncthreads();
            // softmax over S (first 256 threads; syncs unconditional)
            float val = 0.f, ex = 0.f;
            if (tid < 256) {
                val = s_e[tid];
                float m = val;
#pragma unroll
                for (int off = 16; off > 0; off >>= 1)
                    m = fmaxf(m, __shfl_xor_sync(0xffffffffu, m, off));
                if (lane == 0) s_red[w] = m;
            }
            __syncthreads();
            if (tid == 0) {
                float mm = s_red[0];
                for (int i = 1; i < 8; ++i) mm = fmaxf(mm, s_red[i]);
                s_red[8] = mm;
            }
            __syncthreads();
            if (tid < 256) {
                ex = expf(val - s_red[8]);
                float sv = ex;
#pragma unroll
                for (int off = 16; off > 0; off >>= 1)
                    sv += __shfl_xor_sync(0xffffffffu, sv, off);
                if (lane == 0) s_red[16 + w] = sv;
            }
            __syncthreads();
            if (tid == 0) {
                float ss = 0.f;
                for (int i = 0; i < 8; ++i) ss += s_red[16 + i];
                s_red[24] = ss;
            }
            __syncthreads();
            if (tid < 256) {
                float awn = ex / s_red[24];
                s_aw[tid] = awn;
                g_aw[b * NS + tid] = awn;
                g_awc[b * NS + tid] = s_awc[tid] + awn;
                P.out_align[((size_t)b * NT + t) * NS + tid] = awn;
            }
            __syncthreads();
            // ctx = aw @ memory[b] : one thread per enc dim (512)
            {
                const float* mem_b = P.memory + (size_t)b * NS * NENC;
                float a0 = 0.f;
#pragma unroll 8
                for (int s = 0; s < NS; ++s)
                    a0 = fmaf(s_aw[s], mem_b[s * NENC + tid], a0);
                g_ctx[b * NENC + tid] = a0;
            }
        } else if (blk < 144) {
            // decoder-LSTM partial: ah part + dh part (accs live across barrier)
            float* sAh = smf;             // [16][1024]
            float* sDh = smf + NB * NH;   // [16][1024]
            {
                float4* a4 = (float4*)sAh;
                float4* d4 = (float4*)sDh;
                const float4* ga4 = (const float4*)g_ah[p];
                const float4* gd4 = (const float4*)g_dh;
                for (int i = tid; i < NB * NH / 4; i += TPB) { a4[i] = ga4[i]; d4[i] = gd4[i]; }
            }
            __syncthreads();
            const int ul = w >> 1, gA = (w & 1) * 2;
            const int u = (blk - 16) * 8 + ul;
#pragma unroll
            for (int b = 0; b < 16; ++b) { D0[b] = D1[b] = 0.f; }
            gemm2_accum<NH, 8>((const float4*)(P.Wih_d + (size_t)(gA * NH + u) * 1536),
                               (const float4*)(P.Wih_d + (size_t)((gA + 1) * NH + u) * 1536),
                               sAh, lane, D0, D1);
            gemm2_accum<NH, 8>((const float4*)(P.Whh_d + (size_t)(gA * NH + u) * NH),
                               (const float4*)(P.Whh_d + (size_t)((gA + 1) * NH + u) * NH),
                               sDh, lane, D0, D1);
        }
        grid_sync();

        // ================= PHASE 3: finish decoder LSTM with new ctx =================
        if (blk >= 16 && blk < 144) {
            float* sC = smf;               // [16][512]
            float* zb = smf + NB * NENC;   // [4][8][16]
            {
                float4* c4 = (float4*)sC;
                const float4* gc4 = (const float4*)g_ctx;
                for (int i = tid; i < NB * NENC / 4; i += TPB) c4[i] = gc4[i];
            }
            __syncthreads();
            const int ul = w >> 1, gA = (w & 1) * 2;
            const int u = (blk - 16) * 8 + ul;
            gemm2_accum<NENC, 4>((const float4*)(P.Wih_d + (size_t)(gA * NH + u) * 1536 + NH),
                                 (const float4*)(P.Wih_d + (size_t)((gA + 1) * NH + u) * 1536 + NH),
                                 sC, lane, D0, D1);
            wred16(D0); wred16(D1);
            if (lane < 16) {
                zb[gA * 128 + ul * 16 + lane] = pick16(D0, lane);
                zb[(gA + 1) * 128 + ul * 16 + lane] = pick16(D1, lane);
            }
            __syncthreads();
            if (tid < 128) {
                const int ul2 = tid >> 4, b = tid & 15;
                const int uu = (blk - 16) * 8 + ul2;
                float zi = zb[ul2 * 16 + b]       + P.bih_d[uu]          + P.bhh_d[uu];
                float zf = zb[128 + ul2 * 16 + b] + P.bih_d[NH + uu]     + P.bhh_d[NH + uu];
                float zg = zb[256 + ul2 * 16 + b] + P.bih_d[2 * NH + uu] + P.bhh_d[2 * NH + uu];
                float zo = zb[384 + ul2 * 16 + b] + P.bih_d[3 * NH + uu] + P.bhh_d[3 * NH + uu];
                float c = sigf(zf) * g_dc[b * NH + uu] + sigf(zi) * tanhf(zg);
                g_dc[b * NH + uu] = c;
                g_dh[b * NH + uu] = sigf(zo) * tanhf(c);
            }
        }
        grid_sync();
    }

    // final timestep outputs
    if (blk >= 128) write_outputs(P, NT - 1);
}

extern "C" void kernel_launch(void* const* d_in, const int* in_sizes, int n_in,
                              void* d_out, int out_size) {
    Params P;
    P.memory = (const float*)d_in[0];
    P.dec_in = (const float*)d_in[1];
    P.Wpre1  = (const float*)d_in[2];
    P.Wpre2  = (const float*)d_in[3];
    P.Wih_a  = (const float*)d_in[4];
    P.Whh_a  = (const float*)d_in[5];
    P.bih_a  = (const float*)d_in[6];
    P.bhh_a  = (const float*)d_in[7];
    P.Wq     = (const float*)d_in[8];
    P.Wm     = (const float*)d_in[9];
    P.v      = (const float*)d_in[10];
    P.Wc     = (const float*)d_in[11];
    P.Wld    = (const float*)d_in[12];
    P.Wih_d  = (const float*)d_in[13];
    P.Whh_d  = (const float*)d_in[14];
    P.bih_d  = (const float*)d_in[15];
    P.bhh_d  = (const float*)d_in[16];
    P.Wproj  = (const float*)d_in[17];
    P.bproj  = (const float*)d_in[18];
    P.Wgate  = (const float*)d_in[19];
    P.bgate  = (const float*)d_in[20];
    P.mlen   = (const int*)d_in[21];
    float* out = (float*)d_out;
    P.out_mel   = out;
    P.out_gate  = out + NB * NMEL * NT;
    P.out_align = out + NB * NMEL * NT + NB * NT;

    cudaFuncSetAttribute(decoder_kernel, cudaFuncAttributeMaxDynamicSharedMemorySize, SMEM_BYTES);
    decoder_kernel<<<GRID, TPB, SMEM_BYTES>>>(P);
}

// round 15
// speedup vs baseline: 2.2153x; 1.0555x over previous
#include <cuda_runtime.h>

#define NB 16
#define NS 256
#define NT 400
#define NMEL 80
#define NPRE 256
#define NENC 512
#define NH 1024
#define NATT 128
#define NFILT 32
#define KC 31
#define GRID 148
#define TPB 512
#define SMEM_BYTES 131072

struct Params {
    const float *memory, *dec_in, *Wpre1, *Wpre2, *Wih_a, *Whh_a, *bih_a, *bhh_a;
    const float *Wq, *Wm, *v, *Wc, *Wld, *Wih_d, *Whh_d, *bih_d, *bhh_d;
    const float *Wproj, *bproj, *Wgate, *bgate;
    const int* mlen;
    float *out_mel, *out_gate, *out_align;
};

__device__ float g_xs[NT * NB * NPRE];
__device__ float g_pm[NB * NS * NATT];
__device__ float g_ah[2][NB * NH];
__device__ float g_ac[NB * NH];
__device__ float g_dh[NB * NH];
__device__ float g_dc[NB * NH];
__device__ float g_aw[NB * NS];
__device__ float g_awc[NB * NS];
__device__ float g_ctx[NB * NENC];
__device__ unsigned g_cnt = 0;
__device__ unsigned g_gen = 0;

// CG-style barrier: syncthreads + elected-thread release-atomic / acquire-spin.
__device__ __forceinline__ void grid_sync() {
    __syncthreads();
    if (threadIdx.x == 0) {
        unsigned gen = g_gen;
        unsigned prev;
        asm volatile("atom.add.release.gpu.u32 %0, [%1], %2;"
                     : "=r"(prev) : "l"(&g_cnt), "r"(1u) : "memory");
        if (prev == GRID - 1) {
            g_cnt = 0;
            asm volatile("st.release.gpu.u32 [%0], %1;"
                         :: "l"(&g_gen), "r"(gen + 1) : "memory");
        } else {
            unsigned cur;
            do {
                asm volatile("ld.acquire.gpu.u32 %0, [%1];"
                             : "=r"(cur) : "l"(&g_gen) : "memory");
            } while (cur == gen);
        }
    }
    __syncthreads();
}

__device__ __forceinline__ float sigf(float x) { return 1.0f / (1.0f + __expf(-x)); }

__device__ __forceinline__ void wred16(float* a) {
#pragma unroll
    for (int off = 16; off > 0; off >>= 1)
#pragma unroll
        for (int i = 0; i < 16; ++i)
            a[i] += __shfl_xor_sync(0xffffffffu, a[i], off);
}

__device__ __forceinline__ float pick16(const float* a, int lane) {
    float v = a[0];
#pragma unroll
    for (int b = 1; b < 16; ++b)
        if (lane == b) v = a[b];
    return v;
}

__device__ __forceinline__ void wred32(float* a) {
#pragma unroll
    for (int off = 16; off > 0; off >>= 1)
#pragma unroll
        for (int i = 0; i < 32; ++i)
            a[i] += __shfl_xor_sync(0xffffffffu, a[i], off);
}

__device__ __forceinline__ float pick32(const float* a, int lane) {
    float v = a[0];
#pragma unroll
    for (int b = 1; b < 32; ++b)
        if (lane == b) v = a[b];
    return v;
}

// 4-gate-row x 8-batch GEMM accumulation over NCH chunks of 128 k's.
// Each x LDS.128 feeds 16 FFMAs (vs 8 in the 2-row variant) -> half the
// smem crossbar traffic per SM. Weight prefetch 1 chunk ahead.
// av = 32 accumulators laid out [gate0 b0..7 | gate1 | gate2 | gate3].
template <int XSTRIDE, int NCH>
__device__ __forceinline__ void gemm4_accum(
    const float4* __restrict__ W0, const float4* __restrict__ W1,
    const float4* __restrict__ W2, const float4* __restrict__ W3,
    const float* __restrict__ sXb, int lane, float* av)
{
    float4 c0 = W0[lane], c1 = W1[lane], c2 = W2[lane], c3 = W3[lane];
#pragma unroll
    for (int c = 0; c < NCH; ++c) {
        const int nidx = ((c + 1 < NCH) ? (c + 1) : c) * 32 + lane;
        float4 n0 = W0[nidx], n1 = W1[nidx], n2 = W2[nidx], n3 = W3[nidx];
        const float* xb = sXb + c * 128 + lane * 4;
        float4 xc = *(const float4*)(xb);
#pragma unroll
        for (int b = 0; b < 8; ++b) {
            float4 xn = (b < 7) ? *(const float4*)(xb + (b + 1) * XSTRIDE) : xc;
            av[b]      = fmaf(c0.x, xc.x, fmaf(c0.y, xc.y, fmaf(c0.z, xc.z, fmaf(c0.w, xc.w, av[b]))));
            av[8 + b]  = fmaf(c1.x, xc.x, fmaf(c1.y, xc.y, fmaf(c1.z, xc.z, fmaf(c1.w, xc.w, av[8 + b]))));
            av[16 + b] = fmaf(c2.x, xc.x, fmaf(c2.y, xc.y, fmaf(c2.z, xc.z, fmaf(c2.w, xc.w, av[16 + b]))));
            av[24 + b] = fmaf(c3.x, xc.x, fmaf(c3.y, xc.y, fmaf(c3.z, xc.z, fmaf(c3.w, xc.w, av[24 + b]))));
            xc = xn;
        }
        c0 = n0; c1 = n1; c2 = n2; c3 = n3;
    }
}

// mel/gate projection for timestep tq (blocks 128..147)
__device__ void write_outputs(const Params& P, int tq) {
    const int w = threadIdx.x >> 5, lane = threadIdx.x & 31;
    int gw = ((int)blockIdx.x - 128) * 16 + w;   // 0..79 mel rows, 80 gate
    if (gw > 80) return;
    const float* wr = (gw < 80) ? (P.Wproj + gw * (NH + NENC)) : P.Wgate;
    float bias = (gw < 80) ? P.bproj[gw] : P.bgate[0];
    const float4* wr4 = (const float4*)wr;
    const float4* dh4 = (const float4*)g_dh;
    const float4* cx4 = (const float4*)g_ctx;
    float acc[16];
#pragma unroll
    for (int b = 0; b < 16; ++b) acc[b] = 0.f;
    for (int k = lane; k < NH / 4; k += 32) {
        float4 wv = wr4[k];
#pragma unroll
        for (int b = 0; b < 16; ++b) {
            float4 x = dh4[b * 256 + k];
            acc[b] = fmaf(wv.x, x.x, fmaf(wv.y, x.y, fmaf(wv.z, x.z, fmaf(wv.w, x.w, acc[b]))));
        }
    }
    for (int k = lane; k < NENC / 4; k += 32) {
        float4 wv = wr4[256 + k];
#pragma unroll
        for (int b = 0; b < 16; ++b) {
            float4 x = cx4[b * 128 + k];
            acc[b] = fmaf(wv.x, x.x, fmaf(wv.y, x.y, fmaf(wv.z, x.z, fmaf(wv.w, x.w, acc[b]))));
        }
    }
    wred16(acc);
    if (lane < 16) {
        float val = pick16(acc, lane) + bias;
        if (gw < 80) P.out_mel[(lane * NMEL + gw) * NT + tq] = val;
        else         P.out_gate[lane * NT + tq] = val;
    }
}

__global__ void __launch_bounds__(TPB) decoder_kernel(Params P) {
    extern __shared__ float smf[];
    const int blk = blockIdx.x, tid = threadIdx.x;
    const int w = tid >> 5, lane = tid & 31;
    const int h = tid >> 8, lt = tid & 255;   // half-block split for prelude

    // ---------- prelude: zero state ----------
    {
        const int g0 = blk * TPB + tid, gs = GRID * TPB;
        for (int i = g0; i < NB * NH; i += gs) {
            g_ah[0][i] = 0.f; g_ah[1][i] = 0.f;
            g_ac[i] = 0.f; g_dh[i] = 0.f; g_dc[i] = 0.f;
        }
        for (int i = g0; i < NB * NS; i += gs) { g_aw[i] = 0.f; g_awc[i] = 0.f; }
        for (int i = g0; i < NB * NENC; i += gs) g_ctx[i] = 0.f;
        for (int i = g0; i < NB * NPRE; i += gs) g_xs[i] = 0.f;  // xs[0] = prenet(0) = 0
    }
    // prenet for t=1..399 (each half-block processes its own (t,b) pair)
    {
        float* sx = smf + h * 96;          // 80 each
        float* sh1 = smf + 192 + h * 256;  // 256 each
        const int NP = (NT - 1) * NB;
        const int KMAX = (NP + 2 * GRID - 1) / (2 * GRID);
        for (int k = 0; k < KMAX; ++k) {
            int pi = blk * 2 + h + k * 2 * GRID;
            bool act = pi < NP;
            int tt = act ? pi / NB + 1 : 1, b = act ? pi % NB : 0;
            if (act && lt < NMEL) sx[lt] = P.dec_in[(b * NMEL + lt) * NT + (tt - 1)];
            __syncthreads();
            float a1v = 0.f;
            if (act) {
                const float* w1 = P.Wpre1 + lt * NMEL;
#pragma unroll 4
                for (int kk = 0; kk < NMEL; ++kk) a1v += w1[kk] * sx[kk];
                sh1[lt] = fmaxf(a1v, 0.f);
            }
            __syncthreads();
            if (act) {
                const float4* w2 = (const float4*)(P.Wpre2 + lt * NPRE);
                const float4* h4 = (const float4*)sh1;
                float a = 0.f;
#pragma unroll 8
                for (int kk = 0; kk < NPRE / 4; ++kk) {
                    float4 wv = w2[kk], x = h4[kk];
                    a = fmaf(wv.x, x.x, fmaf(wv.y, x.y, fmaf(wv.z, x.z, fmaf(wv.w, x.w, a))));
                }
                g_xs[(tt * NB + b) * NPRE + lt] = fmaxf(a, 0.f);
            }
            __syncthreads();
        }
    }
    // processed memory pm[b][s][a]
    {
        float* srow = smf + h * 512;  // 512 each
        const int NR = NB * NS;
        const int RMAX = (NR + 2 * GRID - 1) / (2 * GRID);
        const int wl = w & 7;
        for (int k = 0; k < RMAX; ++k) {
            int r = blk * 2 + h + k * 2 * GRID;
            bool act = r < NR;
            __syncthreads();
            if (act) for (int i = lt; i < NENC; i += 256) srow[i] = P.memory[(size_t)r * NENC + i];
            __syncthreads();
            if (act) {
                const float4* sr4 = (const float4*)srow;
                for (int a = wl; a < NATT; a += 8) {
                    const float4* wm = (const float4*)(P.Wm + a * NENC);
                    float acc = 0.f;
#pragma unroll
                    for (int kk = lane; kk < NENC / 4; kk += 32) {
                        float4 wv = wm[kk], x = sr4[kk];
                        acc = fmaf(wv.x, x.x, fmaf(wv.y, x.y, fmaf(wv.z, x.z, fmaf(wv.w, x.w, acc))));
                    }
#pragma unroll
                    for (int off = 16; off > 0; off >>= 1)
                        acc += __shfl_xor_sync(0xffffffffu, acc, off);
                    if (lane == 0) g_pm[(size_t)r * NATT + a] = acc;
                }
            }
        }
    }
    grid_sync();

    int p = 0;

    for (int t = 0; t < NT; ++t) {
        float Dv[32];  // decoder accs [gate][8 batches], live phase2 -> phase3

        // ================= PHASE 1: attention LSTM =================
        if (blk < 128) {
            float* sA = smf;                        // [16][768] = [x|ctx]
            float* sH = smf + NB * 768;             // [16][1024] = ah_prev
            float* zb = smf + NB * 768 + NB * NH;   // [4][8][16] gate z values
            {
                float4* sA4 = (float4*)sA;
                const float4* xs4 = (const float4*)(g_xs + (size_t)t * NB * NPRE);
                for (int i = tid; i < NB * NPRE / 4; i += TPB)
                    sA4[(i >> 6) * 192 + (i & 63)] = xs4[i];
                const float4* cx4 = (const float4*)g_ctx;
                for (int i = tid; i < NB * NENC / 4; i += TPB)
                    sA4[(i >> 7) * 192 + 64 + (i & 127)] = cx4[i];
                float4* sH4 = (float4*)sH;
                const float4* ah4 = (const float4*)g_ah[p];
                for (int i = tid; i < NB * NH / 4; i += TPB) sH4[i] = ah4[i];
            }
            __syncthreads();

            const int ul = w >> 1, bh = w & 1;   // unit-in-block, batch half
            const int u = blk * 8 + ul;
            float av[32];
#pragma unroll
            for (int i = 0; i < 32; ++i) av[i] = 0.f;
            gemm4_accum<768, 6>((const float4*)(P.Wih_a + (size_t)u * 768),
                                (const float4*)(P.Wih_a + (size_t)(NH + u) * 768),
                                (const float4*)(P.Wih_a + (size_t)(2 * NH + u) * 768),
                                (const float4*)(P.Wih_a + (size_t)(3 * NH + u) * 768),
                                sA + bh * 8 * 768, lane, av);
            gemm4_accum<NH, 8>((const float4*)(P.Whh_a + (size_t)u * NH),
                               (const float4*)(P.Whh_a + (size_t)(NH + u) * NH),
                               (const float4*)(P.Whh_a + (size_t)(2 * NH + u) * NH),
                               (const float4*)(P.Whh_a + (size_t)(3 * NH + u) * NH),
                               sH + bh * 8 * NH, lane, av);
            wred32(av);
            {
                float val = pick32(av, lane);
                zb[(lane >> 3) * 128 + ul * 16 + bh * 8 + (lane & 7)] = val;
            }
            __syncthreads();
            if (tid < 128) {
                const int ul2 = tid >> 4, b = tid & 15;
                const int uu = blk * 8 + ul2;
                float zi = zb[ul2 * 16 + b]          + P.bih_a[uu]          + P.bhh_a[uu];
                float zf = zb[128 + ul2 * 16 + b]    + P.bih_a[NH + uu]     + P.bhh_a[NH + uu];
                float zg = zb[256 + ul2 * 16 + b]    + P.bih_a[2 * NH + uu] + P.bhh_a[2 * NH + uu];
                float zo = zb[384 + ul2 * 16 + b]    + P.bih_a[3 * NH + uu] + P.bhh_a[3 * NH + uu];
                float c = sigf(zf) * g_ac[b * NH + uu] + sigf(zi) * tanhf(zg);
                g_ac[b * NH + uu] = c;
                g_ah[p ^ 1][b * NH + uu] = sigf(zo) * tanhf(c);
            }
        } else if (t > 0) {
            write_outputs(P, t - 1);
        }
        grid_sync();
        p ^= 1;  // g_ah[p] = new ah

        // ================= PHASE 2 =================
        if (blk < 16) {
            // full attention for batch b = blk
            const int b = blk;
            float* s_aw = smf;             // 256
            float* s_awc = smf + 256;      // 256
            float* s_q = smf + 512;        // 128
            float* s_e = smf + 640;        // 256
            float* s_red = smf + 896;      // 32
            float* s_loc = smf + 1024;     // [s][f] 8192
            float* s_wldT = smf + 9216;    // [f][a] 4096
            float* s_v = smf + 13312;      // 128
            float* s_ah = smf + 13440;     // 1024
            float* s_awp = smf + 14464;    // 288 (aw zero-padded by 15)
            float* s_awcp = smf + 14752;   // 288
            float* s_wcT = smf + 15040;    // [kk][ch][f] 1984
            if (tid < 256) {
                s_aw[tid] = g_aw[b * NS + tid];
                s_awc[tid] = g_awc[b * NS + tid];
            }
            if (tid < 288) {
                bool in = (tid >= 15 && tid < 271);
                s_awp[tid]  = in ? g_aw[b * NS + tid - 15] : 0.f;
                s_awcp[tid] = in ? g_awc[b * NS + tid - 15] : 0.f;
            }
            for (int i = tid; i < NATT * NFILT; i += TPB)
                s_wldT[(i & 31) * NATT + (i >> 5)] = P.Wld[i];  // i = a*32+f -> [f][a]
            for (int i = tid; i < NFILT * 2 * KC; i += TPB) {
                int f = i / (2 * KC), r = i % (2 * KC), ch = r / KC, kk = r % KC;
                s_wcT[(kk * 2 + ch) * 32 + f] = P.Wc[i];
            }
            if (tid < NATT) s_v[tid] = P.v[tid];
            {
                float4* sa4 = (float4*)s_ah;
                const float4* ah4 = (const float4*)(g_ah[p] + b * NH);
                if (tid < NH / 4) sa4[tid] = ah4[tid];
            }
            __syncthreads();
            // q = ah_new[b] @ Wq^T : 16 warps x 8 rows
            const float4* ah4 = (const float4*)s_ah;
            for (int a = w * 8; a < w * 8 + 8; ++a) {
                const float4* wq = (const float4*)(P.Wq + (size_t)a * NH);
                float acc = 0.f;
#pragma unroll
                for (int k = lane; k < NH / 4; k += 32) {
                    float4 wv = wq[k], x = ah4[k];
                    acc = fmaf(wv.x, x.x, fmaf(wv.y, x.y, fmaf(wv.z, x.z, fmaf(wv.w, x.w, acc))));
                }
#pragma unroll
                for (int off = 16; off > 0; off >>= 1)
                    acc += __shfl_xor_sync(0xffffffffu, acc, off);
                if (lane == 0) s_q[a] = acc;
            }
            __syncthreads();
            // location conv: warp w covers s in [w*16, w*16+16), lane = filter f.
            {
                const int sb = w * 16;
                float acc[16];
#pragma unroll
                for (int j = 0; j < 16; ++j) acc[j] = 0.f;
                float ring[16];
#pragma unroll
                for (int j = 0; j < 16; ++j) ring[j] = s_awp[sb + j];
#pragma unroll
                for (int k = 0; k < KC; ++k) {
                    float wk = s_wcT[(k * 2 + 0) * 32 + lane];
#pragma unroll
                    for (int j = 0; j < 16; ++j)
                        acc[j] = fmaf(wk, ring[(k + j) & 15], acc[j]);
                    ring[k & 15] = s_awp[sb + k + 16];
                }
#pragma unroll
                for (int j = 0; j < 16; ++j) ring[j] = s_awcp[sb + j];
#pragma unroll
                for (int k = 0; k < KC; ++k) {
                    float wk = s_wcT[(k * 2 + 1) * 32 + lane];
#pragma unroll
                    for (int j = 0; j < 16; ++j)
                        acc[j] = fmaf(wk, ring[(k + j) & 15], acc[j]);
                    ring[k & 15] = s_awcp[sb + k + 16];
                }
#pragma unroll
                for (int j = 0; j < 16; ++j) s_loc[(sb + j) * 32 + lane] = acc[j];
            }
            __syncthreads();
            // energies: register-tiled GEMM. warp w: s in [w*16,w*16+16),
            // lane covers a = lane + 32*aa. acc init = q[a] + pm[s][a].
            {
                const int sb = w * 16;
                const int ml = P.mlen[b];
                float acc0[16], acc1[16], acc2[16], acc3[16];
                const float* pmb = g_pm + ((size_t)b * NS + sb) * NATT;
                float q0 = s_q[lane], q1 = s_q[lane + 32], q2 = s_q[lane + 64], q3 = s_q[lane + 96];
#pragma unroll
                for (int j = 0; j < 16; ++j) {
                    const float* pr = pmb + j * NATT;
                    acc0[j] = q0 + pr[lane];
                    acc1[j] = q1 + pr[lane + 32];
                    acc2[j] = q2 + pr[lane + 64];
                    acc3[j] = q3 + pr[lane + 96];
                }
#pragma unroll 4
                for (int f = 0; f < NFILT; ++f) {
                    float w0 = s_wldT[f * NATT + lane];
                    float w1 = s_wldT[f * NATT + lane + 32];
                    float w2 = s_wldT[f * NATT + lane + 64];
                    float w3 = s_wldT[f * NATT + lane + 96];
#pragma unroll
                    for (int j = 0; j < 16; ++j) {
                        float lv = s_loc[(sb + j) * 32 + f];
                        acc0[j] = fmaf(w0, lv, acc0[j]);
                        acc1[j] = fmaf(w1, lv, acc1[j]);
                        acc2[j] = fmaf(w2, lv, acc2[j]);
                        acc3[j] = fmaf(w3, lv, acc3[j]);
                    }
                }
                float v0 = s_v[lane], v1 = s_v[lane + 32], v2 = s_v[lane + 64], v3 = s_v[lane + 96];
                float es[16];
#pragma unroll
                for (int j = 0; j < 16; ++j) {
                    es[j] = v0 * tanhf(acc0[j]) + v1 * tanhf(acc1[j])
                          + v2 * tanhf(acc2[j]) + v3 * tanhf(acc3[j]);
                }
                wred16(es);
                if (lane < 16) {
                    int s = sb + lane;
                    s_e[s] = (s < ml) ? pick16(es, lane) : -1e9f;
                }
            }
            __syncthreads();
            // softmax over S (first 256 threads; syncs unconditional)
            float val = 0.f, ex = 0.f;
            if (tid < 256) {
                val = s_e[tid];
                float m = val;
#pragma unroll
                for (int off = 16; off > 0; off >>= 1)
                    m = fmaxf(m, __shfl_xor_sync(0xffffffffu, m, off));
                if (lane == 0) s_red[w] = m;
            }
            __syncthreads();
            if (tid == 0) {
                float mm = s_red[0];
                for (int i = 1; i < 8; ++i) mm = fmaxf(mm, s_red[i]);
                s_red[8] = mm;
            }
            __syncthreads();
            if (tid < 256) {
                ex = expf(val - s_red[8]);
                float sv = ex;
#pragma unroll
                for (int off = 16; off > 0; off >>= 1)
                    sv += __shfl_xor_sync(0xffffffffu, sv, off);
                if (lane == 0) s_red[16 + w] = sv;
            }
            __syncthreads();
            if (tid == 0) {
                float ss = 0.f;
                for (int i = 0; i < 8; ++i) ss += s_red[16 + i];
                s_red[24] = ss;
            }
            __syncthreads();
            if (tid < 256) {
                float awn = ex / s_red[24];
                s_aw[tid] = awn;
                g_aw[b * NS + tid] = awn;
                g_awc[b * NS + tid] = s_awc[tid] + awn;
                P.out_align[((size_t)b * NT + t) * NS + tid] = awn;
            }
            __syncthreads();
            // ctx = aw @ memory[b] : one thread per enc dim (512)
            {
                const float* mem_b = P.memory + (size_t)b * NS * NENC;
                float a0 = 0.f;
#pragma unroll 8
                for (int s = 0; s < NS; ++s)
                    a0 = fmaf(s_aw[s], mem_b[s * NENC + tid], a0);
                g_ctx[b * NENC + tid] = a0;
            }
        } else if (blk < 144) {
            // decoder-LSTM partial: ah part + dh part (accs live across barrier)
            float* sAh = smf;             // [16][1024]
            float* sDh = smf + NB * NH;   // [16][1024]
            {
                float4* a4 = (float4*)sAh;
                float4* d4 = (float4*)sDh;
                const float4* ga4 = (const float4*)g_ah[p];
                const float4* gd4 = (const float4*)g_dh;
                for (int i = tid; i < NB * NH / 4; i += TPB) { a4[i] = ga4[i]; d4[i] = gd4[i]; }
            }
            __syncthreads();
            const int ul = w >> 1, bh = w & 1;
            const int u = (blk - 16) * 8 + ul;
#pragma unroll
            for (int i = 0; i < 32; ++i) Dv[i] = 0.f;
            gemm4_accum<NH, 8>((const float4*)(P.Wih_d + (size_t)u * 1536),
                               (const float4*)(P.Wih_d + (size_t)(NH + u) * 1536),
                               (const float4*)(P.Wih_d + (size_t)(2 * NH + u) * 1536),
                               (const float4*)(P.Wih_d + (size_t)(3 * NH + u) * 1536),
                               sAh + bh * 8 * NH, lane, Dv);
            gemm4_accum<NH, 8>((const float4*)(P.Whh_d + (size_t)u * NH),
                               (const float4*)(P.Whh_d + (size_t)(NH + u) * NH),
                               (const float4*)(P.Whh_d + (size_t)(2 * NH + u) * NH),
                               (const float4*)(P.Whh_d + (size_t)(3 * NH + u) * NH),
                               sDh + bh * 8 * NH, lane, Dv);
        }
        grid_sync();

        // ================= PHASE 3: finish decoder LSTM with new ctx =================
        if (blk >= 16 && blk < 144) {
            float* sC = smf;               // [16][512]
            float* zb = smf + NB * NENC;   // [4][8][16]
            {
                float4* c4 = (float4*)sC;
                const float4* gc4 = (const float4*)g_ctx;
                for (int i = tid; i < NB * NENC / 4; i += TPB) c4[i] = gc4[i];
            }
            __syncthreads();
            const int ul = w >> 1, bh = w & 1;
            const int u = (blk - 16) * 8 + ul;
            gemm4_accum<NENC, 4>((const float4*)(P.Wih_d + (size_t)u * 1536 + NH),
                                 (const float4*)(P.Wih_d + (size_t)(NH + u) * 1536 + NH),
                                 (const float4*)(P.Wih_d + (size_t)(2 * NH + u) * 1536 + NH),
                                 (const float4*)(P.Wih_d + (size_t)(3 * NH + u) * 1536 + NH),
                                 sC + bh * 8 * NENC, lane, Dv);
            wred32(Dv);
            {
                float val = pick32(Dv, lane);
                zb[(lane >> 3) * 128 + ul * 16 + bh * 8 + (lane & 7)] = val;
            }
            __syncthreads();
            if (tid < 128) {
                const int ul2 = tid >> 4, b = tid & 15;
                const int uu = (blk - 16) * 8 + ul2;
                float zi = zb[ul2 * 16 + b]       + P.bih_d[uu]          + P.bhh_d[uu];
                float zf = zb[128 + ul2 * 16 + b] + P.bih_d[NH + uu]     + P.bhh_d[NH + uu];
                float zg = zb[256 + ul2 * 16 + b] + P.bih_d[2 * NH + uu] + P.bhh_d[2 * NH + uu];
                float zo = zb[384 + ul2 * 16 + b] + P.bih_d[3 * NH + uu] + P.bhh_d[3 * NH + uu];
                float c = sigf(zf) * g_dc[b * NH + uu] + sigf(zi) * tanhf(zg);
                g_dc[b * NH + uu] = c;
                g_dh[b * NH + uu] = sigf(zo) * tanhf(c);
            }
        }
        grid_sync();
    }

    // final timestep outputs
    if (blk >= 128) write_outputs(P, NT - 1);
}

extern "C" void kernel_launch(void* const* d_in, const int* in_sizes, int n_in,
                              void* d_out, int out_size) {
    Params P;
    P.memory = (const float*)d_in[0];
    P.dec_in = (const float*)d_in[1];
    P.Wpre1  = (const float*)d_in[2];
    P.Wpre2  = (const float*)d_in[3];
    P.Wih_a  = (const float*)d_in[4];
    P.Whh_a  = (const float*)d_in[5];
    P.bih_a  = (const float*)d_in[6];
    P.bhh_a  = (const float*)d_in[7];
    P.Wq     = (const float*)d_in[8];
    P.Wm     = (const float*)d_in[9];
    P.v      = (const float*)d_in[10];
    P.Wc     = (const float*)d_in[11];
    P.Wld    = (const float*)d_in[12];
    P.Wih_d  = (const float*)d_in[13];
    P.Whh_d  = (const float*)d_in[14];
    P.bih_d  = (const float*)d_in[15];
    P.bhh_d  = (const float*)d_in[16];
    P.Wproj  = (const float*)d_in[17];
    P.bproj  = (const float*)d_in[18];
    P.Wgate  = (const float*)d_in[19];
    P.bgate  = (const float*)d_in[20];
    P.mlen   = (const int*)d_in[21];
    float* out = (float*)d_out;
    P.out_mel   = out;
    P.out_gate  = out + NB * NMEL * NT;
    P.out_align = out + NB * NMEL * NT + NB * NT;

    cudaFuncSetAttribute(decoder_kernel, cudaFuncAttributeMaxDynamicSharedMemorySize, SMEM_BYTES);
    decoder_kernel<<<GRID, TPB, SMEM_BYTES>>>(P);
}